// round 13
// baseline (speedup 1.0000x reference)
#include <cuda_runtime.h>
#include <cstdint>

// PARCOR (reflection) -> LPC coefficients (Levinson step-up), k: [2097152, 25] f32.
//
// Per row: a = k; for m in 2..24: a[1:m] += k[m] * a[1:m][::-1]
// k[m] == a[m] when step m runs, so the recursion is in-place on 25 registers.
//
// R12 change: persistent double-buffered TMA pipeline. Each block owns 16
// tiles (256 rows x 25 f32 = 25.6 KB each). While computing tile i in buf j,
// the load of tile i+1 streams into buf 1-j and the store of tile i-1 drains
// via bulk_group. Buffer reuse guarded by cp.async.bulk.wait_group.read 0
// (prior store has finished READING smem). Removes the load/compute/store
// phase-locking that capped DRAM duty cycle at ~78%.

#define ORDER_P1 25
#define ROWS 256
#define THREADS 256
#define TILE_FLOATS (ROWS * ORDER_P1)        // 6400
#define TILE_BYTES  (TILE_FLOATS * 4)        // 25600
#define TILES_PER_BLOCK 16
#define SMEM_BYTES (2 * TILE_BYTES)          // 51200 -> dynamic smem

extern __shared__ float sbuf[];              // [2][TILE_FLOATS]

__device__ __forceinline__ void mbar_wait(uint32_t s_mbar, int phase)
{
    uint32_t done;
    asm volatile(
        "{\n\t.reg .pred p;\n\t"
        "mbarrier.try_wait.parity.acquire.cta.shared::cta.b64 p, [%1], %2;\n\t"
        "selp.b32 %0, 1, 0, p;\n\t}"
        : "=r"(done) : "r"(s_mbar), "r"((uint32_t)phase) : "memory");
    while (!done) {
        asm volatile(
            "{\n\t.reg .pred p;\n\t"
            "mbarrier.try_wait.parity.acquire.cta.shared::cta.b64 p, [%1], %2, 0x989680;\n\t"
            "selp.b32 %0, 1, 0, p;\n\t}"
            : "=r"(done) : "r"(s_mbar), "r"((uint32_t)phase) : "memory");
    }
}

__global__ __launch_bounds__(THREADS)
void parcor_to_lpc_pipe(const float* __restrict__ kin,
                        float* __restrict__ out)
{
    __shared__ alignas(8) unsigned long long mbar[2];

    const int t = threadIdx.x;
    float* buf0 = sbuf;
    float* buf1 = sbuf + TILE_FLOATS;

    const uint32_t s_buf0 = (uint32_t)__cvta_generic_to_shared(buf0);
    const uint32_t s_buf1 = (uint32_t)__cvta_generic_to_shared(buf1);
    const uint32_t s_mb0  = (uint32_t)__cvta_generic_to_shared(&mbar[0]);
    const uint32_t s_mb1  = (uint32_t)__cvta_generic_to_shared(&mbar[1]);

    if (t == 0) {
        asm volatile("mbarrier.init.shared.b64 [%0], 1;" :: "r"(s_mb0) : "memory");
        asm volatile("mbarrier.init.shared.b64 [%0], 1;" :: "r"(s_mb1) : "memory");
        asm volatile("fence.proxy.async.shared::cta;" ::: "memory");
    }
    __syncthreads();

    const size_t first_tile = (size_t)blockIdx.x * TILES_PER_BLOCK;

    // ---- prologue: load tile 0 into buf0 ----
    if (t == 0) {
        asm volatile("mbarrier.arrive.expect_tx.shared.b64 _, [%0], %1;"
                     :: "r"(s_mb0), "r"((uint32_t)TILE_BYTES) : "memory");
        asm volatile(
            "cp.async.bulk.shared::cta.global.mbarrier::complete_tx::bytes "
            "[%0], [%1], %2, [%3];"
            :: "r"(s_buf0), "l"(kin + first_tile * TILE_FLOATS),
               "r"((uint32_t)TILE_BYTES), "r"(s_mb0)
            : "memory");
    }

    int ph0 = 0, ph1 = 0;

    #pragma unroll 1
    for (int it = 0; it < TILES_PER_BLOCK; it++) {
        const int j = it & 1;
        const uint32_t s_cur  = j ? s_buf1 : s_buf0;
        const uint32_t s_nxt  = j ? s_buf0 : s_buf1;
        const uint32_t s_mbc  = j ? s_mb1  : s_mb0;
        const uint32_t s_mbn  = j ? s_mb0  : s_mb1;
        float* cur = j ? buf1 : buf0;
        const size_t tile = first_tile + it;

        // ---- issue load of tile it+1 into the other buffer ----
        if (t == 0 && it + 1 < TILES_PER_BLOCK) {
            // the other buffer's previous store (tile it-1) must be done
            // READING smem before we overwrite it
            asm volatile("cp.async.bulk.wait_group.read 0;" ::: "memory");
            asm volatile("mbarrier.arrive.expect_tx.shared.b64 _, [%0], %1;"
                         :: "r"(s_mbn), "r"((uint32_t)TILE_BYTES) : "memory");
            asm volatile(
                "cp.async.bulk.shared::cta.global.mbarrier::complete_tx::bytes "
                "[%0], [%1], %2, [%3];"
                :: "r"(s_nxt), "l"(kin + (tile + 1) * TILE_FLOATS),
                   "r"((uint32_t)TILE_BYTES), "r"(s_mbn)
                : "memory");
        }

        // ---- wait for current tile ----
        if (j) { mbar_wait(s_mbc, ph1); ph1 ^= 1; }
        else   { mbar_wait(s_mbc, ph0); ph0 ^= 1; }

        // ---- compute own row (stride-25 smem: gcd(25,32)=1, conflict-free) ----
        float a[ORDER_P1];
        #pragma unroll
        for (int x = 0; x < ORDER_P1; x++) a[x] = cur[t * ORDER_P1 + x];

        #pragma unroll
        for (int m = 2; m <= 24; m++) {
            const float km = a[m];          // == original k[m]
            #pragma unroll
            for (int jj = 1; 2 * jj < m; jj++) {
                const float x = a[jj];
                const float y = a[m - jj];
                a[jj]     = fmaf(km, y, x);
                a[m - jj] = fmaf(km, x, y);
            }
            if ((m & 1) == 0) {
                const int jj = m >> 1;
                a[jj] = fmaf(km, a[jj], a[jj]);   // midpoint: a[j] *= (1+km)
            }
        }

        #pragma unroll
        for (int x = 0; x < ORDER_P1; x++) cur[t * ORDER_P1 + x] = a[x];

        // generic-proxy STS visible to async-proxy bulk store
        asm volatile("fence.proxy.async.shared::cta;" ::: "memory");
        __syncthreads();

        // ---- issue store of current tile (drains in background) ----
        if (t == 0) {
            asm volatile(
                "cp.async.bulk.global.shared::cta.bulk_group [%0], [%1], %2;"
                :: "l"(out + tile * TILE_FLOATS), "r"(s_cur),
                   "r"((uint32_t)TILE_BYTES)
                : "memory");
            asm volatile("cp.async.bulk.commit_group;" ::: "memory");
        }
    }

    // ---- epilogue: make sure last stores complete before block exit ----
    if (t == 0) {
        asm volatile("cp.async.bulk.wait_group 0;" ::: "memory");
    }
}

extern "C" void kernel_launch(void* const* d_in, const int* in_sizes, int n_in,
                              void* d_out, int out_size)
{
    const float* k = (const float*)d_in[0];
    float* out = (float*)d_out;

    const int nrows = in_sizes[0] / ORDER_P1;          // 2097152
    const int ntiles = nrows / ROWS;                   // 8192
    const int grid = ntiles / TILES_PER_BLOCK;         // 512

    static bool attr_set = false;
    if (!attr_set) {
        cudaFuncSetAttribute(parcor_to_lpc_pipe,
                             cudaFuncAttributeMaxDynamicSharedMemorySize,
                             SMEM_BYTES);
        attr_set = true;
    }

    parcor_to_lpc_pipe<<<grid, THREADS, SMEM_BYTES>>>(k, out);
}

// round 14
// speedup vs baseline: 1.0155x; 1.0155x over previous
#include <cuda_runtime.h>
#include <cstdint>

// PARCOR (reflection) -> LPC coefficients (Levinson step-up), k: [2097152, 25] f32.
//
// Per row: a = k; for m in 2..24: a[1:m] += k[m] * a[1:m][::-1]
// k[m] == a[m] when step m runs, so the recursion is in-place on 25 registers.
//
// R12 change: persistent double-buffered TMA pipeline. Each block owns 16
// tiles (256 rows x 25 f32 = 25.6 KB each). While computing tile i in buf j,
// the load of tile i+1 streams into buf 1-j and the store of tile i-1 drains
// via bulk_group. Buffer reuse guarded by cp.async.bulk.wait_group.read 0
// (prior store has finished READING smem). Removes the load/compute/store
// phase-locking that capped DRAM duty cycle at ~78%.

#define ORDER_P1 25
#define ROWS 256
#define THREADS 256
#define TILE_FLOATS (ROWS * ORDER_P1)        // 6400
#define TILE_BYTES  (TILE_FLOATS * 4)        // 25600
#define TILES_PER_BLOCK 16
#define SMEM_BYTES (2 * TILE_BYTES)          // 51200 -> dynamic smem

extern __shared__ float sbuf[];              // [2][TILE_FLOATS]

__device__ __forceinline__ void mbar_wait(uint32_t s_mbar, int phase)
{
    uint32_t done;
    asm volatile(
        "{\n\t.reg .pred p;\n\t"
        "mbarrier.try_wait.parity.acquire.cta.shared::cta.b64 p, [%1], %2;\n\t"
        "selp.b32 %0, 1, 0, p;\n\t}"
        : "=r"(done) : "r"(s_mbar), "r"((uint32_t)phase) : "memory");
    while (!done) {
        asm volatile(
            "{\n\t.reg .pred p;\n\t"
            "mbarrier.try_wait.parity.acquire.cta.shared::cta.b64 p, [%1], %2, 0x989680;\n\t"
            "selp.b32 %0, 1, 0, p;\n\t}"
            : "=r"(done) : "r"(s_mbar), "r"((uint32_t)phase) : "memory");
    }
}

__global__ __launch_bounds__(THREADS)
void parcor_to_lpc_pipe(const float* __restrict__ kin,
                        float* __restrict__ out)
{
    __shared__ alignas(8) unsigned long long mbar[2];

    const int t = threadIdx.x;
    float* buf0 = sbuf;
    float* buf1 = sbuf + TILE_FLOATS;

    const uint32_t s_buf0 = (uint32_t)__cvta_generic_to_shared(buf0);
    const uint32_t s_buf1 = (uint32_t)__cvta_generic_to_shared(buf1);
    const uint32_t s_mb0  = (uint32_t)__cvta_generic_to_shared(&mbar[0]);
    const uint32_t s_mb1  = (uint32_t)__cvta_generic_to_shared(&mbar[1]);

    if (t == 0) {
        asm volatile("mbarrier.init.shared.b64 [%0], 1;" :: "r"(s_mb0) : "memory");
        asm volatile("mbarrier.init.shared.b64 [%0], 1;" :: "r"(s_mb1) : "memory");
        asm volatile("fence.proxy.async.shared::cta;" ::: "memory");
    }
    __syncthreads();

    const size_t first_tile = (size_t)blockIdx.x * TILES_PER_BLOCK;

    // ---- prologue: load tile 0 into buf0 ----
    if (t == 0) {
        asm volatile("mbarrier.arrive.expect_tx.shared.b64 _, [%0], %1;"
                     :: "r"(s_mb0), "r"((uint32_t)TILE_BYTES) : "memory");
        asm volatile(
            "cp.async.bulk.shared::cta.global.mbarrier::complete_tx::bytes "
            "[%0], [%1], %2, [%3];"
            :: "r"(s_buf0), "l"(kin + first_tile * TILE_FLOATS),
               "r"((uint32_t)TILE_BYTES), "r"(s_mb0)
            : "memory");
    }

    int ph0 = 0, ph1 = 0;

    #pragma unroll 1
    for (int it = 0; it < TILES_PER_BLOCK; it++) {
        const int j = it & 1;
        const uint32_t s_cur  = j ? s_buf1 : s_buf0;
        const uint32_t s_nxt  = j ? s_buf0 : s_buf1;
        const uint32_t s_mbc  = j ? s_mb1  : s_mb0;
        const uint32_t s_mbn  = j ? s_mb0  : s_mb1;
        float* cur = j ? buf1 : buf0;
        const size_t tile = first_tile + it;

        // ---- issue load of tile it+1 into the other buffer ----
        if (t == 0 && it + 1 < TILES_PER_BLOCK) {
            // the other buffer's previous store (tile it-1) must be done
            // READING smem before we overwrite it
            asm volatile("cp.async.bulk.wait_group.read 0;" ::: "memory");
            asm volatile("mbarrier.arrive.expect_tx.shared.b64 _, [%0], %1;"
                         :: "r"(s_mbn), "r"((uint32_t)TILE_BYTES) : "memory");
            asm volatile(
                "cp.async.bulk.shared::cta.global.mbarrier::complete_tx::bytes "
                "[%0], [%1], %2, [%3];"
                :: "r"(s_nxt), "l"(kin + (tile + 1) * TILE_FLOATS),
                   "r"((uint32_t)TILE_BYTES), "r"(s_mbn)
                : "memory");
        }

        // ---- wait for current tile ----
        if (j) { mbar_wait(s_mbc, ph1); ph1 ^= 1; }
        else   { mbar_wait(s_mbc, ph0); ph0 ^= 1; }

        // ---- compute own row (stride-25 smem: gcd(25,32)=1, conflict-free) ----
        float a[ORDER_P1];
        #pragma unroll
        for (int x = 0; x < ORDER_P1; x++) a[x] = cur[t * ORDER_P1 + x];

        #pragma unroll
        for (int m = 2; m <= 24; m++) {
            const float km = a[m];          // == original k[m]
            #pragma unroll
            for (int jj = 1; 2 * jj < m; jj++) {
                const float x = a[jj];
                const float y = a[m - jj];
                a[jj]     = fmaf(km, y, x);
                a[m - jj] = fmaf(km, x, y);
            }
            if ((m & 1) == 0) {
                const int jj = m >> 1;
                a[jj] = fmaf(km, a[jj], a[jj]);   // midpoint: a[j] *= (1+km)
            }
        }

        #pragma unroll
        for (int x = 0; x < ORDER_P1; x++) cur[t * ORDER_P1 + x] = a[x];

        // generic-proxy STS visible to async-proxy bulk store
        asm volatile("fence.proxy.async.shared::cta;" ::: "memory");
        __syncthreads();

        // ---- issue store of current tile (drains in background) ----
        if (t == 0) {
            asm volatile(
                "cp.async.bulk.global.shared::cta.bulk_group [%0], [%1], %2;"
                :: "l"(out + tile * TILE_FLOATS), "r"(s_cur),
                   "r"((uint32_t)TILE_BYTES)
                : "memory");
            asm volatile("cp.async.bulk.commit_group;" ::: "memory");
        }
    }

    // ---- epilogue: make sure last stores complete before block exit ----
    if (t == 0) {
        asm volatile("cp.async.bulk.wait_group 0;" ::: "memory");
    }
}

extern "C" void kernel_launch(void* const* d_in, const int* in_sizes, int n_in,
                              void* d_out, int out_size)
{
    const float* k = (const float*)d_in[0];
    float* out = (float*)d_out;

    const int nrows = in_sizes[0] / ORDER_P1;          // 2097152
    const int ntiles = nrows / ROWS;                   // 8192
    const int grid = ntiles / TILES_PER_BLOCK;         // 512

    static bool attr_set = false;
    if (!attr_set) {
        cudaFuncSetAttribute(parcor_to_lpc_pipe,
                             cudaFuncAttributeMaxDynamicSharedMemorySize,
                             SMEM_BYTES);
        attr_set = true;
    }

    parcor_to_lpc_pipe<<<grid, THREADS, SMEM_BYTES>>>(k, out);
}

// round 15
// speedup vs baseline: 1.1167x; 1.0997x over previous
#include <cuda_runtime.h>
#include <cstdint>

// PARCOR (reflection) -> LPC coefficients (Levinson step-up), k: [2097152, 25] f32.
//
// Per row: a = k; for m in 2..24: a[1:m] += k[m] * a[1:m][::-1]
// k[m] == a[m] when step m runs, so the recursion is in-place on 25 registers.
//
// R15: persistent double-buffered TMA pipeline + dynamic work queue.
// R12's static 16-tiles-per-block split left a 512-block grid (3.46 blocks/SM)
// with ~15% whole-tile load imbalance. Now 592 persistent blocks (4/SM) pull
// tile indices from a global atomic counter (skew <= 1 tile), while the
// double-buffer overlap (compute tile i in buf j, TMA-load tile i+1 into
// buf 1-j, bulk-store tile i-1 drains in background) keeps DRAM busy through
// the compute phase.

#define ORDER_P1 25
#define ROWS 256
#define THREADS 256
#define TILE_FLOATS (ROWS * ORDER_P1)        // 6400
#define TILE_BYTES  (TILE_FLOATS * 4)        // 25600
#define SMEM_BYTES (2 * TILE_BYTES)          // 51200 -> dynamic smem
#define GRID_BLOCKS (148 * 4)                // 592 persistent blocks

extern __shared__ float sbuf[];              // [2][TILE_FLOATS]

__device__ unsigned int g_tile_ctr;

__global__ void reset_ctr_kernel() { g_tile_ctr = 0u; }

__device__ __forceinline__ void mbar_wait(uint32_t s_mbar, uint32_t phase)
{
    uint32_t done;
    asm volatile(
        "{\n\t.reg .pred p;\n\t"
        "mbarrier.try_wait.parity.acquire.cta.shared::cta.b64 p, [%1], %2;\n\t"
        "selp.b32 %0, 1, 0, p;\n\t}"
        : "=r"(done) : "r"(s_mbar), "r"(phase) : "memory");
    while (!done) {
        asm volatile(
            "{\n\t.reg .pred p;\n\t"
            "mbarrier.try_wait.parity.acquire.cta.shared::cta.b64 p, [%1], %2, 0x989680;\n\t"
            "selp.b32 %0, 1, 0, p;\n\t}"
            : "=r"(done) : "r"(s_mbar), "r"(phase) : "memory");
    }
}

__global__ __launch_bounds__(THREADS)
void parcor_to_lpc_queue(const float* __restrict__ kin,
                         float* __restrict__ out,
                         int ntiles)
{
    __shared__ alignas(8) unsigned long long mbar[2];
    __shared__ int s_first;      // prologue: does this block have a tile at all?
    __shared__ int s_more[2];    // per-parity continue flags

    const int t = threadIdx.x;
    float* buf[2] = { sbuf, sbuf + TILE_FLOATS };

    const uint32_t s_b[2] = { (uint32_t)__cvta_generic_to_shared(buf[0]),
                              (uint32_t)__cvta_generic_to_shared(buf[1]) };
    const uint32_t s_m[2] = { (uint32_t)__cvta_generic_to_shared(&mbar[0]),
                              (uint32_t)__cvta_generic_to_shared(&mbar[1]) };

    unsigned int cur = 0, nxt = 0;   // meaningful on t==0 only

    if (t == 0) {
        asm volatile("mbarrier.init.shared.b64 [%0], 1;" :: "r"(s_m[0]) : "memory");
        asm volatile("mbarrier.init.shared.b64 [%0], 1;" :: "r"(s_m[1]) : "memory");
        asm volatile("fence.proxy.async.shared::cta;" ::: "memory");

        // ---- prologue: grab first tile, start its load into buf0 ----
        cur = atomicAdd(&g_tile_ctr, 1u);
        s_first = (cur < (unsigned)ntiles);
        if (cur < (unsigned)ntiles) {
            asm volatile("mbarrier.arrive.expect_tx.shared.b64 _, [%0], %1;"
                         :: "r"(s_m[0]), "r"((uint32_t)TILE_BYTES) : "memory");
            asm volatile(
                "cp.async.bulk.shared::cta.global.mbarrier::complete_tx::bytes "
                "[%0], [%1], %2, [%3];"
                :: "r"(s_b[0]), "l"(kin + (size_t)cur * TILE_FLOATS),
                   "r"((uint32_t)TILE_BYTES), "r"(s_m[0])
                : "memory");
        }
    }
    __syncthreads();
    if (!s_first) return;

    uint32_t ph[2] = { 0u, 0u };
    int it = 0;

    #pragma unroll 1
    for (;;) {
        const int j = it & 1;

        // ---- t0: grab next tile; if valid, prefetch it into the other buffer ----
        if (t == 0) {
            nxt = atomicAdd(&g_tile_ctr, 1u);
            s_more[j ^ 1] = (nxt < (unsigned)ntiles);
            if (nxt < (unsigned)ntiles) {
                // the store that last READ buf[j^1] (tile it-1) must be done
                asm volatile("cp.async.bulk.wait_group.read 0;" ::: "memory");
                asm volatile("mbarrier.arrive.expect_tx.shared.b64 _, [%0], %1;"
                             :: "r"(s_m[j ^ 1]), "r"((uint32_t)TILE_BYTES) : "memory");
                asm volatile(
                    "cp.async.bulk.shared::cta.global.mbarrier::complete_tx::bytes "
                    "[%0], [%1], %2, [%3];"
                    :: "r"(s_b[j ^ 1]), "l"(kin + (size_t)nxt * TILE_FLOATS),
                       "r"((uint32_t)TILE_BYTES), "r"(s_m[j ^ 1])
                    : "memory");
            }
        }

        // ---- wait for current tile's load ----
        mbar_wait(s_m[j], ph[j]);
        ph[j] ^= 1u;

        // ---- compute own row (stride-25 smem: gcd(25,32)=1, conflict-free) ----
        float* curb = buf[j];
        float a[ORDER_P1];
        #pragma unroll
        for (int x = 0; x < ORDER_P1; x++) a[x] = curb[t * ORDER_P1 + x];

        #pragma unroll
        for (int m = 2; m <= 24; m++) {
            const float km = a[m];          // == original k[m]
            #pragma unroll
            for (int jj = 1; 2 * jj < m; jj++) {
                const float x = a[jj];
                const float y = a[m - jj];
                a[jj]     = fmaf(km, y, x);
                a[m - jj] = fmaf(km, x, y);
            }
            if ((m & 1) == 0) {
                const int jj = m >> 1;
                a[jj] = fmaf(km, a[jj], a[jj]);   // midpoint: a[j] *= (1+km)
            }
        }

        #pragma unroll
        for (int x = 0; x < ORDER_P1; x++) curb[t * ORDER_P1 + x] = a[x];

        // generic-proxy STS visible to async-proxy bulk store; also publishes s_more
        asm volatile("fence.proxy.async.shared::cta;" ::: "memory");
        __syncthreads();

        // ---- issue store of current tile (drains in background) ----
        if (t == 0) {
            asm volatile(
                "cp.async.bulk.global.shared::cta.bulk_group [%0], [%1], %2;"
                :: "l"(out + (size_t)cur * TILE_FLOATS), "r"(s_b[j]),
                   "r"((uint32_t)TILE_BYTES)
                : "memory");
            asm volatile("cp.async.bulk.commit_group;" ::: "memory");
            cur = nxt;
        }

        if (!s_more[j ^ 1]) break;
        it++;
    }

    // ---- drain last stores before block exit ----
    if (t == 0) {
        asm volatile("cp.async.bulk.wait_group 0;" ::: "memory");
    }
}

extern "C" void kernel_launch(void* const* d_in, const int* in_sizes, int n_in,
                              void* d_out, int out_size)
{
    const float* k = (const float*)d_in[0];
    float* out = (float*)d_out;

    const int nrows = in_sizes[0] / ORDER_P1;          // 2097152
    const int ntiles = nrows / ROWS;                   // 8192

    static bool attr_set = false;
    if (!attr_set) {
        cudaFuncSetAttribute(parcor_to_lpc_queue,
                             cudaFuncAttributeMaxDynamicSharedMemorySize,
                             SMEM_BYTES);
        attr_set = true;
    }

    reset_ctr_kernel<<<1, 1>>>();
    parcor_to_lpc_queue<<<GRID_BLOCKS, THREADS, SMEM_BYTES>>>(k, out, ntiles);
}